// round 5
// baseline (speedup 1.0000x reference)
#include <cuda_runtime.h>

#define T_TOK   32768
#define D_DIM   2048
#define NGROUPS 2048          // 16 tokens per warp-group
#define NWARPS  10

// ---- Blackwell packed f32x2 helpers ----
__device__ __forceinline__ unsigned long long dup2(float x) {
    unsigned long long r;
    asm("mov.b64 %0, {%1, %1};" : "=l"(r) : "f"(x));
    return r;
}
__device__ __forceinline__ void fma2(unsigned long long& a, unsigned long long b, unsigned long long c) {
    asm("fma.rn.f32x2 %0, %1, %2, %0;" : "+l"(a) : "l"(b), "l"(c));
}
__device__ __forceinline__ unsigned long long add2(unsigned long long a, unsigned long long b) {
    unsigned long long r;
    asm("add.rn.f32x2 %0, %1, %2;" : "=l"(r) : "l"(a), "l"(b));
    return r;
}
__device__ __forceinline__ void unpack2(unsigned long long v, float& lo, float& hi) {
    asm("mov.b64 {%0, %1}, %2;" : "=f"(lo), "=f"(hi) : "l"(v));
}

// Persistent kernel: grid = #SMs, 1 CTA/SM, 320 threads (10 warps), 128KB smem.
// Weight smem: per-k 64B row [Ww e0..7 | Wn e0..7], 16B chunks XOR-swizzled by
// ((k>>1)&7)<<4 -> conflict-free LDS.128 for the 16-slice lane mapping.
// Lane = (trow = lane>>4: token octet 0..1, sub = lane&15: 2-k slice).
// Warp group = 16 tokens; each lane accumulates T=8 tokens over its 2 k per iter.
extern "C" __global__ void __launch_bounds__(320, 1)
router_kernel(const float* __restrict__ h,  const float* __restrict__ Ww,
              const float* __restrict__ bw, const float* __restrict__ Wn,
              const float* __restrict__ bn, const float* __restrict__ eps,
              float* __restrict__ out)
{
    extern __shared__ unsigned long long sw[];   // 2048 rows x 64B, swizzled
    char* swb = (char*)sw;

    const int tid = threadIdx.x;

    // Fill weights into smem. Swizzle at 16B granularity: chunk c of row k is at
    // (k*64 + c*16) ^ (((k>>1)&7)<<4); low 4 bytes added after the XOR.
    for (int idx = tid; idx < D_DIM * 8; idx += 320) {
        int k = idx >> 3, e = idx & 7;
        unsigned s = ((unsigned)(k >> 1) & 7u) << 4;
        unsigned cW = (unsigned)(e >> 2);          // chunk 0..1
        unsigned cN = cW + 2u;                     // chunk 2..3
        unsigned offW = (((unsigned)k * 64u + cW * 16u) ^ s) + (unsigned)(e & 3) * 4u;
        unsigned offN = (((unsigned)k * 64u + cN * 16u) ^ s) + (unsigned)(e & 3) * 4u;
        *(float*)(swb + offW) = Ww[idx];
        *(float*)(swb + offN) = Wn[idx];
    }
    __syncthreads();

    const int warp = tid >> 5;
    const int lane = tid & 31;
    const int trow = lane >> 4;          // 0..1 token octet
    const int sub  = lane & 15;          // 0..15 k-slice (2 k per iter)
    const unsigned sx = ((unsigned)sub & 7u) << 4;   // swizzle term (=(k>>1)&7)

    // Groups: round r -> g = r*1520 + warp*gridDim + bid (round 2 lands on
    // warps 0..3 of every SM -> spread).
    for (int g = warp * gridDim.x + blockIdx.x; g < NGROUPS; g += NWARPS * gridDim.x) {
        const int tokb = g * 16 + trow * 8;     // this lane's 8 token streams

        // float2 view: token r at +r*1024, k-offset = sub + i*16 (float2 units)
        const float2* hp = (const float2*)h + (size_t)tokb * (D_DIM / 2) + sub;

        unsigned long long acc[8][8];
        #pragma unroll
        for (int r = 0; r < 8; ++r)
            #pragma unroll
            for (int e = 0; e < 8; ++e) acc[r][e] = 0ull;

        float2 buf[8];
        #pragma unroll
        for (int r = 0; r < 8; ++r) buf[r] = __ldg(hp + r * 1024);

        #pragma unroll 2
        for (int i = 0; i < D_DIM / 32; ++i) {          // 64 iters, 32 k each
            float2 nb[8];
            const int ip = (i + 1 < D_DIM / 32) ? (i + 1) : (D_DIM / 32 - 1);
            #pragma unroll
            for (int r = 0; r < 8; ++r) nb[r] = __ldg(hp + r * 1024 + ip * 16);

            #pragma unroll
            for (int j = 0; j < 2; ++j) {
                const int k = i * 32 + sub * 2 + j;
                const unsigned rowb = (unsigned)k * 64u;
                ulonglong2 w01 = *(const ulonglong2*)(swb + ((rowb +  0u) ^ sx));
                ulonglong2 w23 = *(const ulonglong2*)(swb + ((rowb + 16u) ^ sx));
                ulonglong2 n01 = *(const ulonglong2*)(swb + ((rowb + 32u) ^ sx));
                ulonglong2 n23 = *(const ulonglong2*)(swb + ((rowb + 48u) ^ sx));
                #pragma unroll
                for (int r = 0; r < 8; ++r) {
                    unsigned long long hh = dup2(j ? buf[r].y : buf[r].x);
                    fma2(acc[r][0], w01.x, hh); fma2(acc[r][1], w01.y, hh);
                    fma2(acc[r][2], w23.x, hh); fma2(acc[r][3], w23.y, hh);
                    fma2(acc[r][4], n01.x, hh); fma2(acc[r][5], n01.y, hh);
                    fma2(acc[r][6], n23.x, hh); fma2(acc[r][7], n23.y, hh);
                }
            }

            #pragma unroll
            for (int r = 0; r < 8; ++r) buf[r] = nb[r];
        }

        // Reduce-scatter over the 16 sub lanes (masks 8,4,2 scatter; 1 reduces).
        // Token kept at each stage: upper half iff the corresponding lane bit set.
        unsigned long long a4[4][8];
        {
            const bool hi = (lane & 8) != 0;
            #pragma unroll
            for (int t = 0; t < 4; ++t)
                #pragma unroll
                for (int e = 0; e < 8; ++e) {
                    unsigned long long snd = hi ? acc[t][e]     : acc[t + 4][e];
                    unsigned long long kep = hi ? acc[t + 4][e] : acc[t][e];
                    unsigned long long o = __shfl_xor_sync(0xffffffffu, snd, 8);
                    a4[t][e] = add2(kep, o);
                }
        }
        unsigned long long a2[2][8];
        {
            const bool hi = (lane & 4) != 0;
            #pragma unroll
            for (int t = 0; t < 2; ++t)
                #pragma unroll
                for (int e = 0; e < 8; ++e) {
                    unsigned long long snd = hi ? a4[t][e]     : a4[t + 2][e];
                    unsigned long long kep = hi ? a4[t + 2][e] : a4[t][e];
                    unsigned long long o = __shfl_xor_sync(0xffffffffu, snd, 4);
                    a2[t][e] = add2(kep, o);
                }
        }
        unsigned long long a1[8];
        {
            const bool hi = (lane & 2) != 0;
            #pragma unroll
            for (int e = 0; e < 8; ++e) {
                unsigned long long snd = hi ? a2[0][e] : a2[1][e];
                unsigned long long kep = hi ? a2[1][e] : a2[0][e];
                unsigned long long o = __shfl_xor_sync(0xffffffffu, snd, 2);
                a1[e] = add2(kep, o);
            }
        }
        #pragma unroll
        for (int e = 0; e < 8; ++e) {
            unsigned long long o = __shfl_xor_sync(0xffffffffu, a1[e], 1);
            a1[e] = add2(a1[e], o);
        }

        // Each even lane owns one token: bits from lane 3,2,1 -> token 2,1,0.
        if ((lane & 1) == 0) {
            const int token = (((lane >> 3) & 1) << 2) | (((lane >> 2) & 1) << 1) | ((lane >> 1) & 1);
            const int tok = g * 16 + trow * 8 + token;

            float lg[8], nr[8];
            unpack2(a1[0], lg[0], lg[1]); unpack2(a1[1], lg[2], lg[3]);
            unpack2(a1[2], lg[4], lg[5]); unpack2(a1[3], lg[6], lg[7]);
            unpack2(a1[4], nr[0], nr[1]); unpack2(a1[5], nr[2], nr[3]);
            unpack2(a1[6], nr[4], nr[5]); unpack2(a1[7], nr[6], nr[7]);

            float4 e0 = __ldg((const float4*)(eps + (size_t)tok * 8));
            float4 e1 = __ldg((const float4*)(eps + (size_t)tok * 8) + 1);
            float ee[8] = {e0.x, e0.y, e0.z, e0.w, e1.x, e1.y, e1.z, e1.w};

            float noisy[8];
            #pragma unroll
            for (int e = 0; e < 8; ++e) {
                float x  = nr[e] + bn[e];
                float sp = (x > 0.f) ? (x + log1pf(expf(-x))) : log1pf(expf(x));
                noisy[e] = lg[e] + bw[e] + ee[e] * sp;
            }

            // Full softmax (max-subtracted, matches jax.nn.softmax)
            float m = noisy[0];
            #pragma unroll
            for (int e = 1; e < 8; ++e) m = fmaxf(m, noisy[e]);
            float ex[8], ssum = 0.f;
            #pragma unroll
            for (int e = 0; e < 8; ++e) { ex[e] = expf(noisy[e] - m); ssum += ex[e]; }
            float inv = 1.f / ssum;

            // Top-2, first-occurrence tie-break (matches jax.lax.top_k)
            int i1 = 0; float v1 = noisy[0];
            #pragma unroll
            for (int e = 1; e < 8; ++e) if (noisy[e] > v1) { v1 = noisy[e]; i1 = e; }
            int i2 = -1; float v2 = -3.4e38f;
            #pragma unroll
            for (int e = 0; e < 8; ++e) if (e != i1 && noisy[e] > v2) { v2 = noisy[e]; i2 = e; }

            // Sparse softmax over exactly the two kept entries (others exactly 0)
            float edd = expf(v2 - v1);
            float s1  = 1.f / (1.f + edd);
            float s2  = edd * s1;

            float sp8[8];
            #pragma unroll
            for (int e = 0; e < 8; ++e)
                sp8[e] = (e == i1) ? s1 : ((e == i2) ? s2 : 0.f);

            float* outS = out + (size_t)tok * 8;
            float* outI = out + (size_t)T_TOK * 8  + (size_t)tok * 2;
            float* outF = out + (size_t)T_TOK * 10 + (size_t)tok * 8;

            ((float4*)outS)[0] = make_float4(sp8[0], sp8[1], sp8[2], sp8[3]);
            ((float4*)outS)[1] = make_float4(sp8[4], sp8[5], sp8[6], sp8[7]);
            ((float2*)outI)[0] = make_float2((float)i1, (float)i2);
            ((float4*)outF)[0] = make_float4(ex[0] * inv, ex[1] * inv, ex[2] * inv, ex[3] * inv);
            ((float4*)outF)[1] = make_float4(ex[4] * inv, ex[5] * inv, ex[6] * inv, ex[7] * inv);
        }
    }
}

extern "C" void kernel_launch(void* const* d_in, const int* in_sizes, int n_in,
                              void* d_out, int out_size)
{
    const float* h   = (const float*)d_in[0];
    const float* Ww  = (const float*)d_in[1];
    const float* bw  = (const float*)d_in[2];
    const float* Wn  = (const float*)d_in[3];
    const float* bn  = (const float*)d_in[4];
    const float* eps = (const float*)d_in[5];

    const int smem = D_DIM * 16 * sizeof(float);   // 131072 bytes
    cudaFuncSetAttribute(router_kernel, cudaFuncAttributeMaxDynamicSharedMemorySize, smem);

    int nsm = 148;
    cudaDeviceGetAttribute(&nsm, cudaDevAttrMultiProcessorCount, 0);

    router_kernel<<<nsm, 320, smem>>>(h, Ww, bw, Wn, bn, eps, (float*)d_out);
}

// round 6
// speedup vs baseline: 2.7468x; 2.7468x over previous
#include <cuda_runtime.h>

#define T_TOK   32768
#define D_DIM   2048
#define NGROUPS 2048          // 16 tokens per warp-group
#define NWARPS  14

// ---- Blackwell packed f32x2 helpers ----
__device__ __forceinline__ unsigned long long dup2(float x) {
    unsigned long long r;
    asm("mov.b64 %0, {%1, %1};" : "=l"(r) : "f"(x));
    return r;
}
__device__ __forceinline__ void fma2(unsigned long long& a, unsigned long long b, unsigned long long c) {
    asm("fma.rn.f32x2 %0, %1, %2, %0;" : "+l"(a) : "l"(b), "l"(c));
}
__device__ __forceinline__ unsigned long long add2(unsigned long long a, unsigned long long b) {
    unsigned long long r;
    asm("add.rn.f32x2 %0, %1, %2;" : "=l"(r) : "l"(a), "l"(b));
    return r;
}
__device__ __forceinline__ void unpack2(unsigned long long v, float& lo, float& hi) {
    asm("mov.b64 {%0, %1}, %2;" : "=f"(lo), "=f"(hi) : "l"(v));
}

// Persistent kernel: grid = #SMs, 1 CTA/SM, 448 threads (14 warps), 128KB smem
// of XOR-swizzled weights ([k][Ww e0..7 | Wn e0..7], addr ^= ((k>>2)&7)<<4).
// Lane = (sub = lane>>2: k-slice 0..7, trow = lane&3: token quad 0..3).
// Each lane accumulates T=4 tokens; warp group = 16 tokens; one group per warp
// (2048 groups vs 2128 warp slots) -> ~13.5 concurrently active warps per SM.
extern "C" __global__ void __launch_bounds__(448, 1)
router_kernel(const float* __restrict__ h,  const float* __restrict__ Ww,
              const float* __restrict__ bw, const float* __restrict__ Wn,
              const float* __restrict__ bn, const float* __restrict__ eps,
              float* __restrict__ out)
{
    extern __shared__ unsigned long long sw[];   // 2048 rows x 64B, swizzled
    char* swb = (char*)sw;

    const int tid = threadIdx.x;

    // Fill weights into smem with swizzle.
    for (int idx = tid; idx < D_DIM * 8; idx += 448) {
        int k = idx >> 3, e = idx & 7;
        unsigned sx = ((unsigned)(k >> 2) & 7u) << 4;
        unsigned offW = ((unsigned)k * 64u + (unsigned)e * 4u) ^ sx;
        unsigned offN = ((unsigned)k * 64u + 32u + (unsigned)e * 4u) ^ sx;
        *(float*)(swb + offW) = Ww[idx];
        *(float*)(swb + offN) = Wn[idx];
    }
    __syncthreads();

    const int warp = tid >> 5;
    const int lane = tid & 31;
    const int trow = lane & 3;           // token quad within warp
    const int sub  = lane >> 2;          // k-slice 0..7
    const unsigned subx = (unsigned)sub << 4;   // swizzle term

    // Spread active warps evenly across SMs: same warp-id on every SM first.
    for (int g = warp * gridDim.x + blockIdx.x; g < NGROUPS; g += NWARPS * gridDim.x) {
        const int tokb = g * 16 + trow * 4;     // this lane's 4 token streams

        // one base pointer; token r is at +r*512 float4s (const offsets in SASS)
        const float4* hp = (const float4*)h + (size_t)tokb * (D_DIM / 4) + sub;

        unsigned long long acc[4][8];
        #pragma unroll
        for (int r = 0; r < 4; ++r)
            #pragma unroll
            for (int e = 0; e < 8; ++e) acc[r][e] = 0ull;

        // distance-1 prefetch across 4 token streams
        float4 buf[4];
        #pragma unroll
        for (int r = 0; r < 4; ++r) buf[r] = __ldg(hp + r * 512);

        #pragma unroll 1
        for (int i = 0; i < D_DIM / 32; ++i) {          // 64 iters, 32 k each
            float4 nb[4];
            const int ip = (i + 1 < D_DIM / 32) ? (i + 1) : (D_DIM / 32 - 1);
            #pragma unroll
            for (int r = 0; r < 4; ++r) nb[r] = __ldg(hp + r * 512 + ip * 8);

            const int kbase = i * 32 + sub * 4;
            #pragma unroll
            for (int j = 0; j < 4; ++j) {
                const unsigned base = ((unsigned)(kbase + j) * 64u) ^ subx;
                ulonglong2 w01 = *(const ulonglong2*)(swb + (base ^ 0u));
                ulonglong2 w23 = *(const ulonglong2*)(swb + (base ^ 16u));
                ulonglong2 n01 = *(const ulonglong2*)(swb + (base ^ 32u));
                ulonglong2 n23 = *(const ulonglong2*)(swb + (base ^ 48u));
                #pragma unroll
                for (int r = 0; r < 4; ++r) {
                    float hs = (j == 0) ? buf[r].x : (j == 1) ? buf[r].y
                             : (j == 2) ? buf[r].z : buf[r].w;
                    unsigned long long hh = dup2(hs);
                    fma2(acc[r][0], w01.x, hh); fma2(acc[r][1], w01.y, hh);
                    fma2(acc[r][2], w23.x, hh); fma2(acc[r][3], w23.y, hh);
                    fma2(acc[r][4], n01.x, hh); fma2(acc[r][5], n01.y, hh);
                    fma2(acc[r][6], n23.x, hh); fma2(acc[r][7], n23.y, hh);
                }
            }

            #pragma unroll
            for (int r = 0; r < 4; ++r) buf[r] = nb[r];
        }

        // Butterfly-reduce across the 8 sub lanes (xor 4, 8, 16).
        // Afterwards every lane holds full sums for its trow's 4 tokens.
        #pragma unroll
        for (int s = 4; s <= 16; s <<= 1) {
            #pragma unroll
            for (int r = 0; r < 4; ++r)
                #pragma unroll
                for (int e = 0; e < 8; ++e) {
                    unsigned long long o = __shfl_xor_sync(0xffffffffu, acc[r][e], s);
                    acc[r][e] = add2(acc[r][e], o);
                }
        }

        // Lanes with sub<4 each finish one token: r = sub.
        if (sub < 4) {
            unsigned long long sel[8];
            #pragma unroll
            for (int r = 0; r < 4; ++r)
                if (sub == r) {
                    #pragma unroll
                    for (int e = 0; e < 8; ++e) sel[e] = acc[r][e];
                }

            const int tok = tokb + sub;

            float lg[8], nr[8];
            unpack2(sel[0], lg[0], lg[1]); unpack2(sel[1], lg[2], lg[3]);
            unpack2(sel[2], lg[4], lg[5]); unpack2(sel[3], lg[6], lg[7]);
            unpack2(sel[4], nr[0], nr[1]); unpack2(sel[5], nr[2], nr[3]);
            unpack2(sel[6], nr[4], nr[5]); unpack2(sel[7], nr[6], nr[7]);

            float4 e0 = __ldg((const float4*)(eps + (size_t)tok * 8));
            float4 e1 = __ldg((const float4*)(eps + (size_t)tok * 8) + 1);
            float ee[8] = {e0.x, e0.y, e0.z, e0.w, e1.x, e1.y, e1.z, e1.w};

            float noisy[8];
            #pragma unroll
            for (int e = 0; e < 8; ++e) {
                float x  = nr[e] + bn[e];
                float sp = (x > 0.f) ? (x + log1pf(expf(-x))) : log1pf(expf(x));
                noisy[e] = lg[e] + bw[e] + ee[e] * sp;
            }

            // Full softmax (max-subtracted, matches jax.nn.softmax)
            float m = noisy[0];
            #pragma unroll
            for (int e = 1; e < 8; ++e) m = fmaxf(m, noisy[e]);
            float ex[8], ssum = 0.f;
            #pragma unroll
            for (int e = 0; e < 8; ++e) { ex[e] = expf(noisy[e] - m); ssum += ex[e]; }
            float inv = 1.f / ssum;

            // Top-2, first-occurrence tie-break (matches jax.lax.top_k)
            int i1 = 0; float v1 = noisy[0];
            #pragma unroll
            for (int e = 1; e < 8; ++e) if (noisy[e] > v1) { v1 = noisy[e]; i1 = e; }
            int i2 = -1; float v2 = -3.4e38f;
            #pragma unroll
            for (int e = 0; e < 8; ++e) if (e != i1 && noisy[e] > v2) { v2 = noisy[e]; i2 = e; }

            // Sparse softmax over exactly the two kept entries (others exactly 0)
            float edd = expf(v2 - v1);
            float s1  = 1.f / (1.f + edd);
            float s2  = edd * s1;

            float sp8[8];
            #pragma unroll
            for (int e = 0; e < 8; ++e)
                sp8[e] = (e == i1) ? s1 : ((e == i2) ? s2 : 0.f);

            float* outS = out + (size_t)tok * 8;
            float* outI = out + (size_t)T_TOK * 8  + (size_t)tok * 2;
            float* outF = out + (size_t)T_TOK * 10 + (size_t)tok * 8;

            ((float4*)outS)[0] = make_float4(sp8[0], sp8[1], sp8[2], sp8[3]);
            ((float4*)outS)[1] = make_float4(sp8[4], sp8[5], sp8[6], sp8[7]);
            ((float2*)outI)[0] = make_float2((float)i1, (float)i2);
            ((float4*)outF)[0] = make_float4(ex[0] * inv, ex[1] * inv, ex[2] * inv, ex[3] * inv);
            ((float4*)outF)[1] = make_float4(ex[4] * inv, ex[5] * inv, ex[6] * inv, ex[7] * inv);
        }
    }
}

extern "C" void kernel_launch(void* const* d_in, const int* in_sizes, int n_in,
                              void* d_out, int out_size)
{
    const float* h   = (const float*)d_in[0];
    const float* Ww  = (const float*)d_in[1];
    const float* bw  = (const float*)d_in[2];
    const float* Wn  = (const float*)d_in[3];
    const float* bn  = (const float*)d_in[4];
    const float* eps = (const float*)d_in[5];

    const int smem = D_DIM * 16 * sizeof(float);   // 131072 bytes
    cudaFuncSetAttribute(router_kernel, cudaFuncAttributeMaxDynamicSharedMemorySize, smem);

    int nsm = 148;
    cudaDeviceGetAttribute(&nsm, cudaDevAttrMultiProcessorCount, 0);

    router_kernel<<<nsm, 448, smem>>>(h, Ww, bw, Wn, bn, eps, (float*)d_out);
}

// round 7
// speedup vs baseline: 3.1739x; 1.1555x over previous
#include <cuda_runtime.h>

#define T_TOK   32768
#define D_DIM   2048
#define NE      8
#define NGROUPS (T_TOK / 32)   // 1024 groups of 32 tokens, exact

// ---- Blackwell packed f32x2 helpers ----
__device__ __forceinline__ unsigned long long dup2(float x) {
    unsigned long long r;
    asm("mov.b64 %0, {%1, %1};" : "=l"(r) : "f"(x));
    return r;
}
__device__ __forceinline__ void fma2(unsigned long long& a, unsigned long long b, unsigned long long c) {
    asm("fma.rn.f32x2 %0, %1, %2, %0;" : "+l"(a) : "l"(b), "l"(c));
}
__device__ __forceinline__ unsigned long long add2(unsigned long long a, unsigned long long b) {
    unsigned long long r;
    asm("add.rn.f32x2 %0, %1, %2;" : "=l"(r) : "l"(a), "l"(b));
    return r;
}
__device__ __forceinline__ void unpack2(unsigned long long v, float& lo, float& hi) {
    asm("mov.b64 {%0, %1}, %2;" : "=f"(lo), "=f"(hi) : "l"(v));
}
__device__ __forceinline__ void pf_l2(const void* p) {
    asm volatile("prefetch.global.L2 [%0];" :: "l"(p));
}

// Persistent kernel: grid = #SMs, 1 CTA/SM, 256 threads, 128KB smem of
// XOR-swizzled weights ([k][Ww e0..7 | Wn e0..7], addr ^= ((k>>2)&7)<<4).
// Lane = (sub = lane>>2: k-slice 0..7, trow = lane&3: token octet 0..3).
// Each lane accumulates T=8 tokens -> one 64B weight LDS feeds 64 FMA2.
// h is L2-prefetched 6 iterations ahead so the distance-1 register prefetch
// only has to cover L2-hit latency.
extern "C" __global__ void __launch_bounds__(256, 1)
router_kernel(const float* __restrict__ h,  const float* __restrict__ Ww,
              const float* __restrict__ bw, const float* __restrict__ Wn,
              const float* __restrict__ bn, const float* __restrict__ eps,
              float* __restrict__ out)
{
    extern __shared__ unsigned long long sw[];   // 2048 rows x 64B, swizzled
    char* swb = (char*)sw;

    const int tid = threadIdx.x;

    // Fill weights into smem with swizzle.
    #pragma unroll
    for (int it = 0; it < (D_DIM * NE) / 256; ++it) {
        int idx = tid + it * 256;          // 0..16383
        int k = idx >> 3, e = idx & 7;
        unsigned sx = ((unsigned)(k >> 2) & 7u) << 4;
        unsigned offW = ((unsigned)k * 64u + (unsigned)e * 4u) ^ sx;
        unsigned offN = ((unsigned)k * 64u + 32u + (unsigned)e * 4u) ^ sx;
        *(float*)(swb + offW) = Ww[idx];
        *(float*)(swb + offN) = Wn[idx];
    }
    __syncthreads();

    const int warp = tid >> 5;
    const int lane = tid & 31;
    const int trow = lane & 3;           // token octet within warp
    const int sub  = lane >> 2;          // k-slice 0..7
    const unsigned subx = (unsigned)sub << 4;   // swizzle term

    const int nwarps = gridDim.x * 8;
    // Spread active warps evenly across SMs: same warp-id on every SM first.
    for (int g = warp * gridDim.x + blockIdx.x; g < NGROUPS; g += nwarps) {
        const int tokb = g * 32 + trow * 8;     // this lane's 8 tokens

        // one base pointer; token r is at +r*512 float4s (const offsets in SASS)
        const float4* hp = (const float4*)h + (size_t)tokb * (D_DIM / 4) + sub;

        unsigned long long acc[8][8];
        #pragma unroll
        for (int r = 0; r < 8; ++r)
            #pragma unroll
            for (int e = 0; e < 8; ++e) acc[r][e] = 0ull;

        // L2 prefetch for the first few iterations
        #pragma unroll
        for (int p = 1; p < 6; ++p)
            #pragma unroll
            for (int r = 0; r < 8; ++r) pf_l2(hp + r * 512 + p * 8);

        // distance-1 register prefetch across 8 token streams
        float4 buf[8];
        #pragma unroll
        for (int r = 0; r < 8; ++r) buf[r] = __ldg(hp + r * 512);

        #pragma unroll 2
        for (int i = 0; i < D_DIM / 32; ++i) {          // 64 iters, 32 k each
            // L2 prefetch 6 iterations ahead (clamped to stay in this row)
            const int ipf = (i + 6 < D_DIM / 32) ? (i + 6) : (D_DIM / 32 - 1);
            #pragma unroll
            for (int r = 0; r < 8; ++r) pf_l2(hp + r * 512 + ipf * 8);

            float4 nb[8];
            const int ip = (i + 1 < D_DIM / 32) ? (i + 1) : (D_DIM / 32 - 1);
            #pragma unroll
            for (int r = 0; r < 8; ++r) nb[r] = __ldg(hp + r * 512 + ip * 8);

            const float cc[8][4] = {
                {buf[0].x, buf[0].y, buf[0].z, buf[0].w},
                {buf[1].x, buf[1].y, buf[1].z, buf[1].w},
                {buf[2].x, buf[2].y, buf[2].z, buf[2].w},
                {buf[3].x, buf[3].y, buf[3].z, buf[3].w},
                {buf[4].x, buf[4].y, buf[4].z, buf[4].w},
                {buf[5].x, buf[5].y, buf[5].z, buf[5].w},
                {buf[6].x, buf[6].y, buf[6].z, buf[6].w},
                {buf[7].x, buf[7].y, buf[7].z, buf[7].w}
            };

            const int kbase = i * 32 + sub * 4;
            #pragma unroll
            for (int j = 0; j < 4; ++j) {
                const unsigned base = ((unsigned)(kbase + j) * 64u) ^ subx;
                ulonglong2 w01 = *(const ulonglong2*)(swb + (base ^ 0u));
                ulonglong2 w23 = *(const ulonglong2*)(swb + (base ^ 16u));
                ulonglong2 n01 = *(const ulonglong2*)(swb + (base ^ 32u));
                ulonglong2 n23 = *(const ulonglong2*)(swb + (base ^ 48u));
                #pragma unroll
                for (int r = 0; r < 8; ++r) {
                    unsigned long long hh = dup2(cc[r][j]);
                    fma2(acc[r][0], w01.x, hh); fma2(acc[r][1], w01.y, hh);
                    fma2(acc[r][2], w23.x, hh); fma2(acc[r][3], w23.y, hh);
                    fma2(acc[r][4], n01.x, hh); fma2(acc[r][5], n01.y, hh);
                    fma2(acc[r][6], n23.x, hh); fma2(acc[r][7], n23.y, hh);
                }
            }

            #pragma unroll
            for (int r = 0; r < 8; ++r) buf[r] = nb[r];
        }

        // Butterfly-reduce across the 8 sub lanes (xor 4, 8, 16).
        // Afterwards every lane holds full sums for its trow's 8 tokens.
        #pragma unroll
        for (int s = 4; s <= 16; s <<= 1) {
            #pragma unroll
            for (int r = 0; r < 8; ++r)
                #pragma unroll
                for (int e = 0; e < 8; ++e) {
                    unsigned long long o = __shfl_xor_sync(0xffffffffu, acc[r][e], s);
                    acc[r][e] = add2(acc[r][e], o);
                }
        }

        // Every lane finishes exactly one token: r = sub (0..7).
        {
            unsigned long long sel[8];
            #pragma unroll
            for (int r = 0; r < 8; ++r)
                if (sub == r) {
                    #pragma unroll
                    for (int e = 0; e < 8; ++e) sel[e] = acc[r][e];
                }

            const int tok = tokb + sub;

            float lg[8], nr[8];
            unpack2(sel[0], lg[0], lg[1]); unpack2(sel[1], lg[2], lg[3]);
            unpack2(sel[2], lg[4], lg[5]); unpack2(sel[3], lg[6], lg[7]);
            unpack2(sel[4], nr[0], nr[1]); unpack2(sel[5], nr[2], nr[3]);
            unpack2(sel[6], nr[4], nr[5]); unpack2(sel[7], nr[6], nr[7]);

            float4 e0 = __ldg((const float4*)(eps + (size_t)tok * 8));
            float4 e1 = __ldg((const float4*)(eps + (size_t)tok * 8) + 1);
            float ee[8] = {e0.x, e0.y, e0.z, e0.w, e1.x, e1.y, e1.z, e1.w};

            float noisy[8];
            #pragma unroll
            for (int e = 0; e < 8; ++e) {
                float x  = nr[e] + bn[e];
                float sp = (x > 0.f) ? (x + log1pf(expf(-x))) : log1pf(expf(x));
                noisy[e] = lg[e] + bw[e] + ee[e] * sp;
            }

            // Full softmax (max-subtracted, matches jax.nn.softmax)
            float m = noisy[0];
            #pragma unroll
            for (int e = 1; e < 8; ++e) m = fmaxf(m, noisy[e]);
            float ex[8], ssum = 0.f;
            #pragma unroll
            for (int e = 0; e < 8; ++e) { ex[e] = expf(noisy[e] - m); ssum += ex[e]; }
            float inv = 1.f / ssum;

            // Top-2, first-occurrence tie-break (matches jax.lax.top_k)
            int i1 = 0; float v1 = noisy[0];
            #pragma unroll
            for (int e = 1; e < 8; ++e) if (noisy[e] > v1) { v1 = noisy[e]; i1 = e; }
            int i2 = -1; float v2 = -3.4e38f;
            #pragma unroll
            for (int e = 0; e < 8; ++e) if (e != i1 && noisy[e] > v2) { v2 = noisy[e]; i2 = e; }

            // Sparse softmax over exactly the two kept entries (others exactly 0)
            float edd = expf(v2 - v1);
            float s1  = 1.f / (1.f + edd);
            float s2  = edd * s1;

            float sp8[8];
            #pragma unroll
            for (int e = 0; e < 8; ++e)
                sp8[e] = (e == i1) ? s1 : ((e == i2) ? s2 : 0.f);

            float* outS = out + (size_t)tok * 8;
            float* outI = out + (size_t)T_TOK * 8  + (size_t)tok * 2;
            float* outF = out + (size_t)T_TOK * 10 + (size_t)tok * 8;

            ((float4*)outS)[0] = make_float4(sp8[0], sp8[1], sp8[2], sp8[3]);
            ((float4*)outS)[1] = make_float4(sp8[4], sp8[5], sp8[6], sp8[7]);
            ((float2*)outI)[0] = make_float2((float)i1, (float)i2);
            ((float4*)outF)[0] = make_float4(ex[0] * inv, ex[1] * inv, ex[2] * inv, ex[3] * inv);
            ((float4*)outF)[1] = make_float4(ex[4] * inv, ex[5] * inv, ex[6] * inv, ex[7] * inv);
        }
    }
}

extern "C" void kernel_launch(void* const* d_in, const int* in_sizes, int n_in,
                              void* d_out, int out_size)
{
    const float* h   = (const float*)d_in[0];
    const float* Ww  = (const float*)d_in[1];
    const float* bw  = (const float*)d_in[2];
    const float* Wn  = (const float*)d_in[3];
    const float* bn  = (const float*)d_in[4];
    const float* eps = (const float*)d_in[5];

    const int smem = D_DIM * 16 * sizeof(float);   // 131072 bytes
    cudaFuncSetAttribute(router_kernel, cudaFuncAttributeMaxDynamicSharedMemorySize, smem);

    int nsm = 148;
    cudaDeviceGetAttribute(&nsm, cudaDevAttrMultiProcessorCount, 0);

    router_kernel<<<nsm, 256, smem>>>(h, Ww, bw, Wn, bn, eps, (float*)d_out);
}